// round 15
// baseline (speedup 1.0000x reference)
#include <cuda_runtime.h>
#include <cstdint>

#define NUM_CLASSES 1000
#define FEAT_DIM    256
#define NROWS       262144
#define NBLK        256          // row chunks (one fused-scatter block each)
#define CAP         512          // bucket capacity per class (max count ~330)
#define LAB_CAP     2048         // smem label cache capacity

#define NSTAGE      3            // pipeline stages in the reduce
#define RPS         8            // rows per stage (8 KB)
#define ROW_BYTES   1024         // FEAT_DIM * 4
#define NCONS       128          // consumer threads (4 warps)

// Device-global scratch (no allocation allowed in kernel_launch).
// g_count/g_done start zeroed (static init) and are re-zeroed by the class
// combiner each call, so graph replays always begin from a clean state.
__device__ alignas(16) int   g_count[NUM_CLASSES];
__device__ alignas(16) int   g_done[NUM_CLASSES];
__device__ int   g_idx[NUM_CLASSES * CAP];            // 2 MB bucket array
__device__ float g_part[2 * NUM_CLASSES * FEAT_DIM];  // 2 MB partial sums

// ---------------------------------------------------------------------------
// mbarrier / bulk-async / PDL helpers
// ---------------------------------------------------------------------------
__device__ __forceinline__ uint32_t s2u(const void* p) {
    return (uint32_t)__cvta_generic_to_shared(p);
}
__device__ __forceinline__ void mbar_init(uint32_t a, uint32_t cnt) {
    asm volatile("mbarrier.init.shared.b64 [%0], %1;" :: "r"(a), "r"(cnt) : "memory");
}
__device__ __forceinline__ void mbar_expect_tx(uint32_t a, uint32_t bytes) {
    asm volatile("mbarrier.arrive.expect_tx.shared.b64 _, [%0], %1;"
                 :: "r"(a), "r"(bytes) : "memory");
}
__device__ __forceinline__ void mbar_arrive(uint32_t a) {
    asm volatile("mbarrier.arrive.shared.b64 _, [%0];" :: "r"(a) : "memory");
}
__device__ __forceinline__ void mbar_wait(uint32_t a, uint32_t parity) {
    asm volatile(
        "{\n\t.reg .pred P;\n"
        "WL%=:\n\t"
        "mbarrier.try_wait.parity.acquire.cta.shared::cta.b64 P, [%0], %1;\n\t"
        "@P bra WD%=;\n\t"
        "bra WL%=;\n"
        "WD%=:\n\t}"
        :: "r"(a), "r"(parity) : "memory");
}
__device__ __forceinline__ void bulk_ld(uint32_t dst, const void* src,
                                        uint32_t bytes, uint32_t mbar) {
    asm volatile(
        "cp.async.bulk.shared::cta.global.mbarrier::complete_tx::bytes "
        "[%0], [%1], %2, [%3];"
        :: "r"(dst), "l"(src), "r"(bytes), "r"(mbar) : "memory");
}
__device__ __forceinline__ void pdl_wait() {
    asm volatile("griddepcontrol.wait;" ::: "memory");
}
__device__ __forceinline__ void pdl_trigger() {
    asm volatile("griddepcontrol.launch_dependents;" ::: "memory");
}

// ---------------------------------------------------------------------------
// Kernel 1 (fused prep): per-chunk hist -> bucket reservation -> scatter.
// 256 blocks x 1024 threads, one row per thread. (R12-R14 proven version.)
// ---------------------------------------------------------------------------
__global__ void __launch_bounds__(1024)
k_prep(const int* __restrict__ labels, int n, int rpb) {
    __shared__ int h[NUM_CLASSES];
    __shared__ int lab[LAB_CAP];
    int b = blockIdx.x;
    int t = threadIdx.x;
    int base = b * rpb;
    bool cache = (rpb <= LAB_CAP);

    for (int i = t; i < NUM_CLASSES; i += 1024) h[i] = 0;
    __syncthreads();

    // Phase A: histogram + label caching.
    for (int j = t; j < rpb; j += 1024) {
        int r = base + j;
        int c = (r < n) ? labels[r] : -1;
        if (cache) lab[j] = c;
        if (c >= 0) atomicAdd(&h[c], 1);
    }
    __syncthreads();

    // Phase B: reserve ranges; h[c] becomes this block's cursor base.
    for (int c = t; c < NUM_CLASSES; c += 1024) {
        int v = h[c];
        h[c] = (v > 0) ? atomicAdd(&g_count[c], v) : 0;
    }
    __syncthreads();

    // Phase C: scatter (labels from smem).
    for (int j = t; j < rpb; j += 1024) {
        int r = base + j;
        if (r < n) {
            int c = cache ? lab[j] : labels[r];
            int pos = atomicAdd(&h[c], 1);
            g_idx[c * CAP + pos] = r;
        }
    }
    pdl_trigger();
}

// ---------------------------------------------------------------------------
// Kernel 2: warp-specialized pipelined reduce, 2 blocks per class.
// Block bid = 2c+h reduces half of class c's bucket. Both halves write 1KB
// partial sums to g_part; the second block to finish (ticket via g_done[c])
// combines both partials with the prototype and writes the output.
// ---------------------------------------------------------------------------
__global__ void __launch_bounds__(160, 8)
k_reduce(const char* __restrict__ featsB,
         const float* __restrict__ protos,
         float* __restrict__ out) {
    __shared__ float4 stage[NSTAGE][RPS * 64];          // 3 x 8KB
    __shared__ float4 part4[2][64];                     // 2KB combine buffer
    __shared__ alignas(8) unsigned long long mbar[2 * NSTAGE];
    __shared__ int s_comb;

    int bid = blockIdx.x;
    int c   = bid >> 1;
    int hh  = bid & 1;
    int t   = threadIdx.x;

    // ---- PDL prolog: independent of k_prep's outputs ----
    float p0 = 0.f, p1 = 0.f;
    if (t < NCONS) {
        p0 = protos[c * FEAT_DIM + t];
        p1 = protos[c * FEAT_DIM + t + NCONS];
    }
    if (t == 0) {
        #pragma unroll
        for (int s = 0; s < NSTAGE; s++) {
            mbar_init(s2u(&mbar[2 * s]), 1);        // full: tx-completion
            mbar_init(s2u(&mbar[2 * s + 1]), 4);    // empty: 4 consumer warps
        }
    }
    __syncthreads();

    // ---- wait for k_prep, then read its outputs ----
    pdl_wait();
    int cnt   = g_count[c];
    int n0    = (cnt + 1) >> 1;                // rows in half 0
    int myCnt = hh ? (cnt - n0) : n0;
    int start = c * CAP + hh * n0;
    int nIter = (myCnt + RPS - 1) / RPS;

    if (t >= NCONS) {
        // ---- producer warp ----
        int lane = t - NCONS;
        int idxReg = 0;
        int s = 0, wrap = 0;
        for (int i = 0; i < nIter; i++) {
            if ((i & 3) == 0) {           // refill 32 indices (4 iterations)
                int p = i * RPS + lane;
                idxReg = (p < myCnt) ? g_idx[start + p] : 0;
            }
            if (wrap > 0)
                mbar_wait(s2u(&mbar[2 * s + 1]), (unsigned)((wrap - 1) & 1));
            int m = min(RPS, myCnt - i * RPS);
            int row = __shfl_sync(0xffffffffu, idxReg, ((i & 3) << 3) + (lane & 7));
            if (lane == 0)
                mbar_expect_tx(s2u(&mbar[2 * s]), (uint32_t)m * ROW_BYTES);
            __syncwarp();
            if (lane < m)
                bulk_ld(s2u(&stage[s][0]) + (uint32_t)lane * ROW_BYTES,
                        featsB + (long)row * ROW_BYTES,
                        ROW_BYTES, s2u(&mbar[2 * s]));
            if (++s == NSTAGE) { s = 0; wrap++; }
        }
    } else {
        // ---- consumer warps (4 warps, 128 threads) ----
        int grp = t >> 6;     // 0..1
        int col = t & 63;
        float4 a0 = make_float4(0.f, 0.f, 0.f, 0.f);
        float4 a1 = make_float4(0.f, 0.f, 0.f, 0.f);
        float4 a2 = make_float4(0.f, 0.f, 0.f, 0.f);
        float4 a3 = make_float4(0.f, 0.f, 0.f, 0.f);
        int s = 0, ph = 0;
        for (int i = 0; i < nIter; i++) {
            mbar_wait(s2u(&mbar[2 * s]), (unsigned)ph);
            int m = min(RPS, myCnt - i * RPS);
            if (grp < m) {
                float4 v = stage[s][grp * 64 + col];
                a0.x += v.x; a0.y += v.y; a0.z += v.z; a0.w += v.w;
            }
            if (grp + 2 < m) {
                float4 v = stage[s][(grp + 2) * 64 + col];
                a1.x += v.x; a1.y += v.y; a1.z += v.z; a1.w += v.w;
            }
            if (grp + 4 < m) {
                float4 v = stage[s][(grp + 4) * 64 + col];
                a2.x += v.x; a2.y += v.y; a2.z += v.z; a2.w += v.w;
            }
            if (grp + 6 < m) {
                float4 v = stage[s][(grp + 6) * 64 + col];
                a3.x += v.x; a3.y += v.y; a3.z += v.z; a3.w += v.w;
            }
            __syncwarp();
            if ((t & 31) == 0) mbar_arrive(s2u(&mbar[2 * s + 1]));
            if (++s == NSTAGE) { s = 0; ph ^= 1; }
        }
        float4 a = make_float4((a0.x + a1.x) + (a2.x + a3.x),
                               (a0.y + a1.y) + (a2.y + a3.y),
                               (a0.z + a1.z) + (a2.z + a3.z),
                               (a0.w + a1.w) + (a2.w + a3.w));
        part4[grp][col] = a;
    }
    __syncthreads();

    // ---- write this half's 256-float partial sum ----
    const float* part = (const float*)part4;
    if (t < NCONS) {
        float s0 = part[0 * 256 + t] + part[1 * 256 + t];
        float s1 = part[0 * 256 + t + NCONS] + part[1 * 256 + t + NCONS];
        g_part[bid * FEAT_DIM + t]         = s0;
        g_part[bid * FEAT_DIM + t + NCONS] = s1;
    }
    __threadfence();          // order partial writes before the ticket
    __syncthreads();

    if (t == 0) {
        int old = atomicAdd(&g_done[c], 1);
        s_comb = (old == 1);  // second finisher combines
    }
    __syncthreads();

    if (s_comb) {
        __threadfence();      // acquire the other half's partials
        if (t < NCONS) {
            float inv = (cnt > 0) ? 0.1f / (float)cnt : 0.f;
            int e = 2 * c * FEAT_DIM;          // even half base
            int o = e + FEAT_DIM;              // odd half base
            float s0 = g_part[e + t]         + g_part[o + t];
            float s1 = g_part[e + t + NCONS] + g_part[o + t + NCONS];
            float r0 = (cnt > 0) ? (0.9f * p0 + s0 * inv) : p0;
            float r1 = (cnt > 0) ? (0.9f * p1 + s1 * inv) : p1;
            out[c * FEAT_DIM + t]         = r0;
            out[c * FEAT_DIM + t + NCONS] = r1;
        }
        // Reset per-class state for the next graph replay (both blocks of
        // this class have already read g_count: their reads precede their
        // tickets, and this block observed both tickets).
        if (t == 0) { g_done[c] = 0; g_count[c] = 0; }
    }
}

// ---------------------------------------------------------------------------
// Launch: k_prep, then k_reduce (2000 blocks) with PDL overlap.
// ---------------------------------------------------------------------------
extern "C" void kernel_launch(void* const* d_in, const int* in_sizes, int n_in,
                              void* d_out, int out_size) {
    const float* features   = (const float*)d_in[0];
    const int*   labels     = (const int*)d_in[1];
    const float* prototypes = (const float*)d_in[2];
    float*       out        = (float*)d_out;

    int n   = in_sizes[1];
    int rpb = (n + NBLK - 1) / NBLK;   // rows per block-chunk (1024)

    k_prep<<<NBLK, 1024>>>(labels, n, rpb);

    cudaLaunchConfig_t cfg = {};
    cfg.gridDim  = dim3(2 * NUM_CLASSES, 1, 1);
    cfg.blockDim = dim3(160, 1, 1);
    cfg.dynamicSmemBytes = 0;
    cudaLaunchAttribute attrs[1];
    attrs[0].id = cudaLaunchAttributeProgrammaticStreamSerialization;
    attrs[0].val.programmaticStreamSerializationAllowed = 1;
    cfg.attrs = attrs;
    cfg.numAttrs = 1;
    cudaLaunchKernelEx(&cfg, k_reduce, (const char*)features, prototypes, out);
}

// round 16
// speedup vs baseline: 1.0529x; 1.0529x over previous
#include <cuda_runtime.h>
#include <cstdint>

#define NUM_CLASSES 1000
#define FEAT_DIM    256
#define NROWS       262144
#define NBLK        256          // row chunks (one fused-scatter block each)
#define CAP         512          // bucket capacity per class (max count ~330)
#define LAB_CAP     2048         // smem label cache capacity

#define NSTAGE      3            // pipeline stages in the reduce
#define RPS         8            // rows per stage (8 KB)
#define ROW_BYTES   1024         // FEAT_DIM * 4
#define NCONS       128          // consumer threads (4 warps)

// Device-global scratch (no allocation allowed in kernel_launch).
// g_count starts zeroed (static init) and is re-zeroed by k_reduce each call,
// so graph replays always begin from a clean state.
__device__ alignas(16) int g_count[NUM_CLASSES];
__device__ int g_idx[NUM_CLASSES * CAP];     // 2 MB bucket array

// ---------------------------------------------------------------------------
// mbarrier / bulk-async / PDL helpers
// ---------------------------------------------------------------------------
__device__ __forceinline__ uint32_t s2u(const void* p) {
    return (uint32_t)__cvta_generic_to_shared(p);
}
__device__ __forceinline__ void mbar_init(uint32_t a, uint32_t cnt) {
    asm volatile("mbarrier.init.shared.b64 [%0], %1;" :: "r"(a), "r"(cnt) : "memory");
}
__device__ __forceinline__ void mbar_expect_tx(uint32_t a, uint32_t bytes) {
    asm volatile("mbarrier.arrive.expect_tx.shared.b64 _, [%0], %1;"
                 :: "r"(a), "r"(bytes) : "memory");
}
__device__ __forceinline__ void mbar_arrive(uint32_t a) {
    asm volatile("mbarrier.arrive.shared.b64 _, [%0];" :: "r"(a) : "memory");
}
__device__ __forceinline__ void mbar_wait(uint32_t a, uint32_t parity) {
    asm volatile(
        "{\n\t.reg .pred P;\n"
        "WL%=:\n\t"
        "mbarrier.try_wait.parity.acquire.cta.shared::cta.b64 P, [%0], %1;\n\t"
        "@P bra WD%=;\n\t"
        "bra WL%=;\n"
        "WD%=:\n\t}"
        :: "r"(a), "r"(parity) : "memory");
}
__device__ __forceinline__ void bulk_ld(uint32_t dst, const void* src,
                                        uint32_t bytes, uint32_t mbar) {
    asm volatile(
        "cp.async.bulk.shared::cta.global.mbarrier::complete_tx::bytes "
        "[%0], [%1], %2, [%3];"
        :: "r"(dst), "l"(src), "r"(bytes), "r"(mbar) : "memory");
}
__device__ __forceinline__ void pdl_wait() {
    asm volatile("griddepcontrol.wait;" ::: "memory");
}
__device__ __forceinline__ void pdl_trigger() {
    asm volatile("griddepcontrol.launch_dependents;" ::: "memory");
}

// ---------------------------------------------------------------------------
// Kernel 1 (fused prep): per-chunk hist -> bucket reservation -> scatter.
// 256 blocks x 1024 threads, one row per thread.
//   Phase A: smem histogram + smem label cache (single global label read).
//   Phase B: one atomicAdd(&g_count[c], h[c]) per present class reserves a
//            contiguous range in class c's bucket; base overwrites h[c].
//   Phase C: scatter rows via smem cursors into g_idx[c*CAP + base + k].
// ---------------------------------------------------------------------------
__global__ void __launch_bounds__(1024)
k_prep(const int* __restrict__ labels, int n, int rpb) {
    __shared__ int h[NUM_CLASSES];
    __shared__ int lab[LAB_CAP];
    int b = blockIdx.x;
    int t = threadIdx.x;
    int base = b * rpb;
    bool cache = (rpb <= LAB_CAP);

    for (int i = t; i < NUM_CLASSES; i += 1024) h[i] = 0;
    __syncthreads();

    // Phase A: histogram + label caching.
    for (int j = t; j < rpb; j += 1024) {
        int r = base + j;
        int c = (r < n) ? labels[r] : -1;
        if (cache) lab[j] = c;
        if (c >= 0) atomicAdd(&h[c], 1);
    }
    __syncthreads();

    // Phase B: reserve ranges; h[c] becomes this block's cursor base.
    for (int c = t; c < NUM_CLASSES; c += 1024) {
        int v = h[c];
        h[c] = (v > 0) ? atomicAdd(&g_count[c], v) : 0;
    }
    __syncthreads();

    // Phase C: scatter (labels from smem).
    for (int j = t; j < rpb; j += 1024) {
        int r = base + j;
        if (r < n) {
            int c = cache ? lab[j] : labels[r];
            int pos = atomicAdd(&h[c], 1);
            g_idx[c * CAP + pos] = r;
        }
    }
    pdl_trigger();
}

// ---------------------------------------------------------------------------
// Kernel 2: warp-specialized pipelined reduce with a PDL prolog (mbarrier
// init + prototype prefetch overlap k_prep's tail). 160 threads =
// 4 consumer warps + 1 producer warp; 3-stage cp.async.bulk pipeline.
// Class c's rows live in g_idx[c*CAP .. c*CAP+cnt). Resets g_count[c].
// ---------------------------------------------------------------------------
__global__ void __launch_bounds__(160, 8)
k_reduce(const char* __restrict__ featsB,
         const float* __restrict__ protos,
         float* __restrict__ out) {
    __shared__ float4 stage[NSTAGE][RPS * 64];          // 3 x 8KB
    __shared__ float4 part4[2][64];                     // 2KB combine buffer
    __shared__ alignas(8) unsigned long long mbar[2 * NSTAGE]; // full/empty pairs

    int c = blockIdx.x;
    int t = threadIdx.x;
    int start = c * CAP;

    // ---- PDL prolog: independent of k_prep's outputs ----
    float p0 = 0.f, p1 = 0.f;
    if (t < NCONS) {
        p0 = protos[c * FEAT_DIM + t];
        p1 = protos[c * FEAT_DIM + t + NCONS];
    }
    if (t == 0) {
        #pragma unroll
        for (int s = 0; s < NSTAGE; s++) {
            mbar_init(s2u(&mbar[2 * s]), 1);        // full: tx-completion
            mbar_init(s2u(&mbar[2 * s + 1]), 4);    // empty: 4 consumer warps
        }
    }
    __syncthreads();

    // ---- wait for k_prep to finish, then read its outputs ----
    pdl_wait();
    int cnt   = g_count[c];
    int nIter = (cnt + RPS - 1) / RPS;
    __syncthreads();
    if (t == 0) g_count[c] = 0;   // reset for next graph replay

    if (t >= NCONS) {
        // ---- producer warp ----
        int lane = t - NCONS;
        int idxReg = 0;
        int s = 0, wrap = 0;
        for (int i = 0; i < nIter; i++) {
            if ((i & 3) == 0) {           // refill 32 indices (4 iterations worth)
                int p = i * RPS + lane;
                idxReg = (p < cnt) ? g_idx[start + p] : 0;
            }
            if (wrap > 0)
                mbar_wait(s2u(&mbar[2 * s + 1]), (unsigned)((wrap - 1) & 1));
            int m = min(RPS, cnt - i * RPS);
            int row = __shfl_sync(0xffffffffu, idxReg, ((i & 3) << 3) + (lane & 7));
            if (lane == 0)
                mbar_expect_tx(s2u(&mbar[2 * s]), (uint32_t)m * ROW_BYTES);
            __syncwarp();
            if (lane < m)
                bulk_ld(s2u(&stage[s][0]) + (uint32_t)lane * ROW_BYTES,
                        featsB + (long)row * ROW_BYTES,
                        ROW_BYTES, s2u(&mbar[2 * s]));
            if (++s == NSTAGE) { s = 0; wrap++; }
        }
    } else {
        // ---- consumer warps (4 warps, 128 threads) ----
        int grp = t >> 6;     // 0..1
        int col = t & 63;
        float4 a0 = make_float4(0.f, 0.f, 0.f, 0.f);
        float4 a1 = make_float4(0.f, 0.f, 0.f, 0.f);
        float4 a2 = make_float4(0.f, 0.f, 0.f, 0.f);
        float4 a3 = make_float4(0.f, 0.f, 0.f, 0.f);
        int s = 0, ph = 0;
        for (int i = 0; i < nIter; i++) {
            mbar_wait(s2u(&mbar[2 * s]), (unsigned)ph);
            int m = min(RPS, cnt - i * RPS);
            if (grp < m) {
                float4 v = stage[s][grp * 64 + col];
                a0.x += v.x; a0.y += v.y; a0.z += v.z; a0.w += v.w;
            }
            if (grp + 2 < m) {
                float4 v = stage[s][(grp + 2) * 64 + col];
                a1.x += v.x; a1.y += v.y; a1.z += v.z; a1.w += v.w;
            }
            if (grp + 4 < m) {
                float4 v = stage[s][(grp + 4) * 64 + col];
                a2.x += v.x; a2.y += v.y; a2.z += v.z; a2.w += v.w;
            }
            if (grp + 6 < m) {
                float4 v = stage[s][(grp + 6) * 64 + col];
                a3.x += v.x; a3.y += v.y; a3.z += v.z; a3.w += v.w;
            }
            __syncwarp();
            if ((t & 31) == 0) mbar_arrive(s2u(&mbar[2 * s + 1]));
            if (++s == NSTAGE) { s = 0; ph ^= 1; }
        }
        float4 a = make_float4((a0.x + a1.x) + (a2.x + a3.x),
                               (a0.y + a1.y) + (a2.y + a3.y),
                               (a0.z + a1.z) + (a2.z + a3.z),
                               (a0.w + a1.w) + (a2.w + a3.w));
        part4[grp][col] = a;
    }

    __syncthreads();

    if (t < NCONS) {
        const float* part = (const float*)part4;   // part[g*256 + column]
        float inv = (cnt > 0) ? 0.1f / (float)cnt : 0.f;
        float s0 = part[0 * 256 + t] + part[1 * 256 + t];
        float s1 = part[0 * 256 + t + NCONS] + part[1 * 256 + t + NCONS];
        float r0 = (cnt > 0) ? (0.9f * p0 + s0 * inv) : p0;
        float r1 = (cnt > 0) ? (0.9f * p1 + s1 * inv) : p1;
        out[c * FEAT_DIM + t]         = r0;
        out[c * FEAT_DIM + t + NCONS] = r1;
    }
}

// ---------------------------------------------------------------------------
// Launch: k_prep, then k_reduce with programmatic dependent launch so its
// prolog overlaps k_prep's tail.
// ---------------------------------------------------------------------------
extern "C" void kernel_launch(void* const* d_in, const int* in_sizes, int n_in,
                              void* d_out, int out_size) {
    const float* features   = (const float*)d_in[0];
    const int*   labels     = (const int*)d_in[1];
    const float* prototypes = (const float*)d_in[2];
    float*       out        = (float*)d_out;

    int n   = in_sizes[1];
    int rpb = (n + NBLK - 1) / NBLK;   // rows per block-chunk (1024)

    k_prep<<<NBLK, 1024>>>(labels, n, rpb);

    cudaLaunchConfig_t cfg = {};
    cfg.gridDim  = dim3(NUM_CLASSES, 1, 1);
    cfg.blockDim = dim3(160, 1, 1);
    cfg.dynamicSmemBytes = 0;
    cudaLaunchAttribute attrs[1];
    attrs[0].id = cudaLaunchAttributeProgrammaticStreamSerialization;
    attrs[0].val.programmaticStreamSerializationAllowed = 1;
    cfg.attrs = attrs;
    cfg.numAttrs = 1;
    cudaLaunchKernelEx(&cfg, k_reduce, (const char*)features, prototypes, out);
}